// round 3
// baseline (speedup 1.0000x reference)
#include <cuda_runtime.h>

#define BB 32
#define SS 1024
#define DD 512
#define DD4 (DD/4)
#define MAXL 8192     // durations in [1,8], S=1024 -> mel_len <= 8192
#define CHUNKS 9      // 32*9 = 288 blocks = one full wave at 2 blocks/SM

// ---------------------------------------------------------------------------
// Fully fused kernel: one block = (batch b, chunk c) of output rows.
//  - block re-scans durations[b] into smem (warp-shuffle scan, cheap/redundant)
//  - each of the 32 warps owns a CONTIGUOUS span of <=32 output rows:
//      * one binary search per lane (row base+lane), shfl-broadcast per row
//      * consecutive rows sharing a source token reuse registers (no reload)
//      * 4x LDG.128 per new source row, 4x STG.128 streaming per output row
//  - writes mel_len / mel_mask tails inline
// ---------------------------------------------------------------------------
__global__ __launch_bounds__(1024, 2)
void lr_fused_kernel(const int*    __restrict__ dur,
                     const float4* __restrict__ x4,
                     float4*       __restrict__ out4,
                     float*        __restrict__ mel_len_out,
                     float*        __restrict__ mask_out,
                     int max_len, int rows_per_chunk, int has_tail)
{
    __shared__ int s[SS];
    __shared__ int warp_sums[32];

    const int b     = blockIdx.x / CHUNKS;
    const int chunk = blockIdx.x % CHUNKS;
    const int tid   = threadIdx.x;
    const int lane  = tid & 31;
    const int wid   = tid >> 5;

    // ---- inclusive scan of durations[b] into smem ----
    int v = dur[b * SS + tid];
    #pragma unroll
    for (int off = 1; off < 32; off <<= 1) {
        int n = __shfl_up_sync(0xffffffff, v, off);
        if (lane >= off) v += n;
    }
    if (lane == 31) warp_sums[wid] = v;
    __syncthreads();
    if (wid == 0) {
        int w = warp_sums[lane];
        #pragma unroll
        for (int off = 1; off < 32; off <<= 1) {
            int n = __shfl_up_sync(0xffffffff, w, off);
            if (lane >= off) w += n;
        }
        warp_sums[lane] = w;
    }
    __syncthreads();
    s[tid] = v + ((wid > 0) ? warp_sums[wid - 1] : 0);
    __syncthreads();

    const int mel = s[SS - 1];
    if (has_tail && chunk == 0 && tid == 0) mel_len_out[b] = (float)mel;

    // ---- per-warp contiguous row span ----
    const int t0   = chunk * rows_per_chunk;
    const int t1   = min(t0 + rows_per_chunk, max_len);
    const int span = (rows_per_chunk + 31) >> 5;      // <= 32 by construction
    const int wbase = t0 + wid * span;
    const int wend  = min(wbase + span, t1);
    const int nrows = wend - wbase;
    if (nrows <= 0) return;

    // one binary search per lane: row t = wbase + lane
    const int t = wbase + lane;
    int src = -1;                                     // -1 => padding (zeros)
    if (t < wend) {
        if (t < mel) {
            int lo = 0, hi = SS - 1;                  // first i with s[i] > t
            #pragma unroll
            for (int it = 0; it < 10; ++it) {
                if (lo < hi) {
                    int mid = (lo + hi) >> 1;
                    if (s[mid] > t) hi = mid; else lo = mid + 1;
                }
            }
            src = lo;
        }
        if (has_tail) mask_out[b * max_len + t] = (t >= mel) ? 1.0f : 0.0f;
    }

    // ---- copy phase: iterate the warp's rows, reuse registers across runs ----
    const float4* __restrict__ xb = x4 + (long)b * SS * DD4;
    long out_p = ((long)b * max_len + wbase) * DD4 + lane;

    int last_src = -2;
    float4 v0 = make_float4(0.f, 0.f, 0.f, 0.f);
    float4 v1 = v0, v2 = v0, v3 = v0;

    for (int j = 0; j < nrows; ++j) {
        const int sj = __shfl_sync(0xffffffff, src, j);   // warp-uniform
        if (sj != last_src) {
            if (sj < 0) {
                v0 = v1 = v2 = v3 = make_float4(0.f, 0.f, 0.f, 0.f);
            } else {
                const long ib = (long)sj * DD4 + lane;
                v0 = __ldg(&xb[ib]);
                v1 = __ldg(&xb[ib + 32]);
                v2 = __ldg(&xb[ib + 64]);
                v3 = __ldg(&xb[ib + 96]);
            }
            last_src = sj;
        }
        __stcs(&out4[out_p],      v0);
        __stcs(&out4[out_p + 32], v1);
        __stcs(&out4[out_p + 64], v2);
        __stcs(&out4[out_p + 96], v3);
        out_p += DD4;
    }
}

// ---------------------------------------------------------------------------
extern "C" void kernel_launch(void* const* d_in, const int* in_sizes, int n_in,
                              void* d_out, int out_size)
{
    const float* x   = (const float*)d_in[0];
    const int*   dur = (const int*)d_in[1];
    float*       out = (float*)d_out;

    // Recover max_len from out_size.
    // Layout A (tuple of 3): out_size = B*L*D + B + B*L  ->  L = (out_size-B)/(B*(D+1))
    // Layout B (expanded only): out_size = B*L*D         ->  L = out_size/(B*D)
    long L;
    int has_tail;
    long os = (long)out_size;
    if ((os - BB) > 0 && ((os - BB) % ((long)BB * (DD + 1))) == 0) {
        L = (os - BB) / ((long)BB * (DD + 1));
        has_tail = 1;
    } else {
        L = os / ((long)BB * DD);
        has_tail = 0;
    }
    if (L <= 0 || L > MAXL) return;

    const int max_len = (int)L;
    const int rows_per_chunk = (max_len + CHUNKS - 1) / CHUNKS;  // <= 911 -> span <= 32

    float* mel_len_out = out + (long)BB * max_len * DD;   // B floats
    float* mask_out    = mel_len_out + BB;                // B*L floats

    lr_fused_kernel<<<BB * CHUNKS, 1024>>>(
        dur, (const float4*)x, (float4*)out,
        mel_len_out, mask_out, max_len, rows_per_chunk, has_tail);
}